// round 13
// baseline (speedup 1.0000x reference)
#include <cuda_runtime.h>

#define A 128
#define S 512
#define D 768
#define V 30522
#define NL 10
#define LW 5
#define MASK_ID 103

#define NCH 16         // attention chunks per row (equal split of valid range)
#define JT 12          // dense j tiles (64 each)
#define KT 24          // dense k splits (64 each)
#define NTILE 64

// ---------------- scratch (device globals; no allocs allowed) ---------------
__device__ float g_m[A * NCH];
__device__ float g_l[A * NCH];
__device__ float g_acc[A * NCH * D];
__device__ float g_x[A * 2 * D];          // [att | mask_logit]
__device__ float g_hpart[KT * A * D];

// ---------------- kernel 1: fused prep + online attention, equal-split ------
__global__ void __launch_bounds__(256, 3) attn_fused(const float* __restrict__ bert,
                                                     const int* __restrict__ ids,
                                                     const int* __restrict__ length,
                                                     const float* __restrict__ Wsen,
                                                     const float* __restrict__ bsen,
                                                     float* __restrict__ out) {
    int c = blockIdx.x, a = blockIdx.y, tid = threadIdx.x;
    int warp = tid >> 5, lane = tid & 31;
    int len = length[a];
    int per = (len + NCH - 1) / NCH;          // rows per chunk (equal split)
    int s_lo = 3 + c * per;
    int s_hi = min(3 + len, s_lo + per);
    int idxc = a * NCH + c;
    if (s_lo >= s_hi) {
        if (tid == 0) { g_m[idxc] = -1e30f; g_l[idxc] = 0.f; }
        return;
    }

    __shared__ int mp;
    __shared__ __align__(16) float mls[D];
    __shared__ __align__(16) float pacc[8][D];
    __shared__ float pm[8], pl[8];
    __shared__ float red0[8], red1[8];

    if (tid == 0) mp = S;
    __syncthreads();
    #pragma unroll
    for (int s = tid; s < S; s += 256)
        if (ids[a * S + s] == MASK_ID) atomicMin(&mp, s);
    __syncthreads();

    const float* mlrow = bert + ((size_t)a * S + mp) * D;
    for (int d = tid; d < D; d += 256) mls[d] = mlrow[d];
    __syncthreads();

    if (c == 0) {
        for (int d = tid; d < D; d += 256)
            g_x[a * 2 * D + D + d] = mls[d];
        const float* r0 = bert + (size_t)a * S * D;
        float p0 = 0.f, p1 = 0.f;
        for (int d = tid; d < D; d += 256) {
            float v = r0[d];
            p0 = fmaf(v, Wsen[d], p0);
            p1 = fmaf(v, Wsen[D + d], p1);
        }
        #pragma unroll
        for (int off = 16; off; off >>= 1) {
            p0 += __shfl_xor_sync(0xffffffffu, p0, off);
            p1 += __shfl_xor_sync(0xffffffffu, p1, off);
        }
        if (lane == 0) { red0[warp] = p0; red1[warp] = p1; }
        __syncthreads();
        if (tid == 0) {
            float s0 = 0.f, s1 = 0.f;
            #pragma unroll
            for (int i = 0; i < 8; i++) { s0 += red0[i]; s1 += red1[i]; }
            out[a * 2 + 0] = s0 + bsen[0];
            out[a * 2 + 1] = s1 + bsen[1];
        }
    }

    const float4* ml4 = (const float4*)mls;

    float m_run = -1e30f, l_run = 0.f;
    float acc[24];
    #pragma unroll
    for (int i = 0; i < 24; i++) acc[i] = 0.f;

    for (int s = s_lo + warp; s < s_hi; s += 8) {
        const float4* r = (const float4*)(bert + ((size_t)a * S + s) * D);
        float4 v[6];
        #pragma unroll
        for (int k = 0; k < 6; k++) v[k] = r[lane + 32 * k];
        float sc = 0.f;
        #pragma unroll
        for (int k = 0; k < 6; k++) {
            float4 u = ml4[lane + 32 * k];
            sc = fmaf(v[k].x, u.x, sc); sc = fmaf(v[k].y, u.y, sc);
            sc = fmaf(v[k].z, u.z, sc); sc = fmaf(v[k].w, u.w, sc);
        }
        #pragma unroll
        for (int off = 16; off; off >>= 1)
            sc += __shfl_xor_sync(0xffffffffu, sc, off);

        float m_new = fmaxf(m_run, sc);
        float f = __expf(m_run - m_new);
        float e = __expf(sc - m_new);
        l_run = fmaf(l_run, f, e);
        #pragma unroll
        for (int k = 0; k < 6; k++) {
            acc[4*k+0] = fmaf(e, v[k].x, acc[4*k+0] * f);
            acc[4*k+1] = fmaf(e, v[k].y, acc[4*k+1] * f);
            acc[4*k+2] = fmaf(e, v[k].z, acc[4*k+2] * f);
            acc[4*k+3] = fmaf(e, v[k].w, acc[4*k+3] * f);
        }
        m_run = m_new;
    }

    float4* pa = (float4*)pacc[warp];
    #pragma unroll
    for (int k = 0; k < 6; k++)
        pa[lane + 32 * k] = make_float4(acc[4*k], acc[4*k+1], acc[4*k+2], acc[4*k+3]);
    if (lane == 0) { pm[warp] = m_run; pl[warp] = l_run; }
    __syncthreads();

    // merge 8 warp partials (some warps may be empty: pm=-1e30, pl=0, acc=0)
    float M = pm[0];
    #pragma unroll
    for (int w = 1; w < 8; w++) M = fmaxf(M, pm[w]);
    float scale[8]; float L = 0.f;
    #pragma unroll
    for (int w = 0; w < 8; w++) {
        scale[w] = __expf(pm[w] - M);
        L = fmaf(pl[w], scale[w], L);
    }
    size_t ob = (size_t)idxc * D;
    for (int d = tid; d < D; d += 256) {
        float vsum = 0.f;
        #pragma unroll
        for (int w = 0; w < 8; w++)
            vsum = fmaf(pacc[w][d], scale[w], vsum);
        g_acc[ob + d] = vsum;
    }
    if (tid == 0) { g_m[idxc] = M; g_l[idxc] = L; }
}

// ---------------- kernel 2: combine partial softmax, write att into x -------
__global__ void attn_combine() {
    int a = blockIdx.x, tid = threadIdx.x;
    __shared__ float sscale[NCH];
    __shared__ float sLinv;
    if (tid == 0) {
        float M = -1e30f;
        #pragma unroll
        for (int c = 0; c < NCH; c++) M = fmaxf(M, g_m[a * NCH + c]);
        float L = 0.f;
        #pragma unroll
        for (int c = 0; c < NCH; c++) {
            float lc = g_l[a * NCH + c];
            float s = (lc > 0.f) ? expf(g_m[a * NCH + c] - M) : 0.f;
            sscale[c] = s;
            L += lc * s;
        }
        sLinv = 1.f / L;
    }
    __syncthreads();
    float inv = sLinv;
    for (int d = tid; d < D; d += 256) {
        float v = 0.f;
        #pragma unroll
        for (int c = 0; c < NCH; c++)
            v = fmaf(g_acc[(size_t)(a * NCH + c) * D + d], sscale[c], v);
        g_x[a * 2 * D + d] = v * inv;
    }
}

// ---------------- kernel 3: dense GEMM split-K partials (KT=24, grid 288) ---
__global__ void dense_partial(const float* __restrict__ Wd) {
    int jt = blockIdx.x;   // 0..11 -> j tile of 64
    int kt = blockIdx.y;   // 0..23 -> k slice of 64
    int tid = threadIdx.x;
    int j0 = jt * NTILE, k0 = kt * 64;
    __shared__ float xs[128][32];
    __shared__ float wst[32][NTILE + 1];
    int tj = tid & 31, tg = tid >> 5;
    float c0[16], c1[16];
    #pragma unroll
    for (int i = 0; i < 16; i++) { c0[i] = 0.f; c1[i] = 0.f; }

    for (int kk = 0; kk < 2; kk++) {
        __syncthreads();
        int kb = k0 + kk * 32;
        #pragma unroll
        for (int i = 0; i < 16; i++) {
            int idx = tid + i * 256;
            int aa = idx >> 5, k = idx & 31;
            xs[aa][k] = g_x[(size_t)aa * (2 * D) + kb + k];
        }
        #pragma unroll
        for (int i = 0; i < 8; i++) {
            int idx = tid + i * 256;
            int j = idx >> 5, k = idx & 31;
            wst[k][j] = Wd[(size_t)(j0 + j) * (2 * D) + kb + k];
        }
        __syncthreads();
        #pragma unroll
        for (int k = 0; k < 32; k++) {
            float w0 = wst[k][tj], w1 = wst[k][tj + 32];
            #pragma unroll
            for (int i = 0; i < 16; i++) {
                float xv = xs[tg + 8 * i][k];
                c0[i] = fmaf(xv, w0, c0[i]);
                c1[i] = fmaf(xv, w1, c1[i]);
            }
        }
    }
    size_t base = (size_t)kt * A * D;
    #pragma unroll
    for (int i = 0; i < 16; i++) {
        int aa = tg + 8 * i;
        g_hpart[base + (size_t)aa * D + j0 + tj] = c0[i];
        g_hpart[base + (size_t)aa * D + j0 + 32 + tj] = c1[i];
    }
}

// ---------------- kernel 4: fused split-K reduce + tanh + vocab head --------
__global__ void __launch_bounds__(768) tail_kernel(const float* __restrict__ bd,
                                                   const float* __restrict__ Wp,
                                                   const float* __restrict__ bp,
                                                   const int* __restrict__ lwords,
                                                   const float* __restrict__ Wlab,
                                                   float* __restrict__ out) {
    int a = blockIdx.x, tid = threadIdx.x;
    __shared__ __align__(16) float hs[D];
    __shared__ float4 redsm[768];
    __shared__ float lp[NL * LW];

    int q = tid % 192;          // float4 index within the 768-wide row
    int g = tid / 192;          // slice group 0..3 (6 slices each)

    float4 s = make_float4(0.f, 0.f, 0.f, 0.f);
    #pragma unroll
    for (int t = g * 6; t < g * 6 + 6; t++) {
        float4 v = *(const float4*)(g_hpart + (size_t)t * A * D + (size_t)a * D + q * 4);
        s.x += v.x; s.y += v.y; s.z += v.z; s.w += v.w;
    }
    redsm[tid] = s;
    __syncthreads();
    if (g == 0) {
        float4 b = *(const float4*)(bd + q * 4);
        float4 s1 = redsm[q + 192], s2 = redsm[q + 384], s3 = redsm[q + 576];
        float4 r;
        r.x = tanhf(b.x + s.x + s1.x + s2.x + s3.x);
        r.y = tanhf(b.y + s.y + s1.y + s2.y + s3.y);
        r.z = tanhf(b.z + s.z + s1.z + s2.z + s3.z);
        r.w = tanhf(b.w + s.w + s1.w + s2.w + s3.w);
        *(float4*)(hs + q * 4) = r;
    }
    __syncthreads();

    int warp = tid >> 5, lane = tid & 31;   // 24 warps
    const float4* h4 = (const float4*)hs;
    for (int t = warp; t < NL * LW; t += 24) {
        int word = lwords[t];
        const float4* wr = (const float4*)(Wp + (size_t)word * D);
        float acc = 0.f;
        #pragma unroll
        for (int k = 0; k < 6; k++) {
            float4 v = wr[lane + 32 * k];
            float4 u = h4[lane + 32 * k];
            acc = fmaf(v.x, u.x, acc); acc = fmaf(v.y, u.y, acc);
            acc = fmaf(v.z, u.z, acc); acc = fmaf(v.w, u.w, acc);
        }
        #pragma unroll
        for (int off = 16; off; off >>= 1)
            acc += __shfl_xor_sync(0xffffffffu, acc, off);
        if (lane == 0) lp[t] = tanhf(acc + bp[word]);
    }
    __syncthreads();
    if (tid < 2 * NL) {
        int k = tid / NL, l = tid % NL;
        float o = 0.f;
        #pragma unroll
        for (int w = 0; w < LW; w++)
            o = fmaf(lp[l * LW + w], Wlab[(l * 2 + k) * LW + w], o);
        out[2 * A + a * (2 * NL) + k * NL + l] = o;
    }
}

// ---------------------------------------------------------------------------
extern "C" void kernel_launch(void* const* d_in, const int* in_sizes, int n_in,
                              void* d_out, int out_size) {
    const float* bert   = (const float*)d_in[0];
    const int*   ids    = (const int*)d_in[1];
    const int*   length = (const int*)d_in[2];
    const int*   lwords = (const int*)d_in[3];
    const float* Wsen   = (const float*)d_in[4];
    const float* bsen   = (const float*)d_in[5];
    const float* Wd     = (const float*)d_in[6];
    const float* bd     = (const float*)d_in[7];
    const float* Wp     = (const float*)d_in[8];
    const float* bp     = (const float*)d_in[9];
    const float* Wlab   = (const float*)d_in[10];
    float* out = (float*)d_out;

    attn_fused<<<dim3(NCH, A), 256>>>(bert, ids, length, Wsen, bsen, out);
    attn_combine<<<A, 256>>>();
    dense_partial<<<dim3(JT, KT), 256>>>(Wd);
    tail_kernel<<<A, 768>>>(bd, Wp, bp, lwords, Wlab, out);
}

// round 14
// speedup vs baseline: 1.2495x; 1.2495x over previous
#include <cuda_runtime.h>

#define A 128
#define S 512
#define D 768
#define V 30522
#define NL 10
#define LW 5
#define MASK_ID 103

#define NCH 4          // attention s-chunks per row
#define CHUNK 128
#define JT 12          // dense j tiles (64 each)
#define KT 24          // dense k splits (64 each)
#define NTILE 64

// ---------------- scratch (device globals; no allocs allowed) ---------------
__device__ float g_m[A * NCH];
__device__ float g_l[A * NCH];
__device__ float g_acc[A * NCH * D];
__device__ float g_x[A * 2 * D];          // [att | mask_logit]
__device__ float g_hpart[KT * A * D];

// ---------------- kernel 1: fused prep + online attention, 1-wave chunks ----
__global__ void __launch_bounds__(256, 3) attn_fused(const float* __restrict__ bert,
                                                     const int* __restrict__ ids,
                                                     const int* __restrict__ length,
                                                     const float* __restrict__ Wsen,
                                                     const float* __restrict__ bsen,
                                                     float* __restrict__ out) {
    int c = blockIdx.x, a = blockIdx.y, tid = threadIdx.x;
    int warp = tid >> 5, lane = tid & 31;
    int len = length[a];
    int s_lo = max(3, c * CHUNK);
    int s_hi = min((c + 1) * CHUNK, 3 + len);
    int idxc = a * NCH + c;
    if (s_lo >= s_hi) {
        if (tid == 0) { g_m[idxc] = -1e30f; g_l[idxc] = 0.f; }
        return;
    }

    __shared__ int mp;
    __shared__ __align__(16) float mls[D];
    __shared__ __align__(16) float pacc[8][D];
    __shared__ float pm[8], pl[8];
    __shared__ float red0[8], red1[8];

    if (tid == 0) mp = S;
    __syncthreads();
    #pragma unroll
    for (int s = tid; s < S; s += 256)
        if (ids[a * S + s] == MASK_ID) atomicMin(&mp, s);
    __syncthreads();

    const float* mlrow = bert + ((size_t)a * S + mp) * D;
    for (int d = tid; d < D; d += 256) mls[d] = mlrow[d];
    __syncthreads();

    if (c == 0) {
        for (int d = tid; d < D; d += 256)
            g_x[a * 2 * D + D + d] = mls[d];
        const float* r0 = bert + (size_t)a * S * D;
        float p0 = 0.f, p1 = 0.f;
        for (int d = tid; d < D; d += 256) {
            float v = r0[d];
            p0 = fmaf(v, Wsen[d], p0);
            p1 = fmaf(v, Wsen[D + d], p1);
        }
        #pragma unroll
        for (int off = 16; off; off >>= 1) {
            p0 += __shfl_xor_sync(0xffffffffu, p0, off);
            p1 += __shfl_xor_sync(0xffffffffu, p1, off);
        }
        if (lane == 0) { red0[warp] = p0; red1[warp] = p1; }
        __syncthreads();
        if (tid == 0) {
            float s0 = 0.f, s1 = 0.f;
            #pragma unroll
            for (int i = 0; i < 8; i++) { s0 += red0[i]; s1 += red1[i]; }
            out[a * 2 + 0] = s0 + bsen[0];
            out[a * 2 + 1] = s1 + bsen[1];
        }
    }

    const float4* ml4 = (const float4*)mls;

    float m_run = -1e30f, l_run = 0.f;
    float acc[24];
    #pragma unroll
    for (int i = 0; i < 24; i++) acc[i] = 0.f;

    for (int s = s_lo + warp; s < s_hi; s += 8) {
        const float4* r = (const float4*)(bert + ((size_t)a * S + s) * D);
        float4 v[6];
        #pragma unroll
        for (int k = 0; k < 6; k++) v[k] = r[lane + 32 * k];
        float sc = 0.f;
        #pragma unroll
        for (int k = 0; k < 6; k++) {
            float4 u = ml4[lane + 32 * k];
            sc = fmaf(v[k].x, u.x, sc); sc = fmaf(v[k].y, u.y, sc);
            sc = fmaf(v[k].z, u.z, sc); sc = fmaf(v[k].w, u.w, sc);
        }
        #pragma unroll
        for (int off = 16; off; off >>= 1)
            sc += __shfl_xor_sync(0xffffffffu, sc, off);

        float m_new = fmaxf(m_run, sc);
        float f = __expf(m_run - m_new);
        float e = __expf(sc - m_new);
        l_run = fmaf(l_run, f, e);
        #pragma unroll
        for (int k = 0; k < 6; k++) {
            acc[4*k+0] = fmaf(e, v[k].x, acc[4*k+0] * f);
            acc[4*k+1] = fmaf(e, v[k].y, acc[4*k+1] * f);
            acc[4*k+2] = fmaf(e, v[k].z, acc[4*k+2] * f);
            acc[4*k+3] = fmaf(e, v[k].w, acc[4*k+3] * f);
        }
        m_run = m_new;
    }

    float4* pa = (float4*)pacc[warp];
    #pragma unroll
    for (int k = 0; k < 6; k++)
        pa[lane + 32 * k] = make_float4(acc[4*k], acc[4*k+1], acc[4*k+2], acc[4*k+3]);
    if (lane == 0) { pm[warp] = m_run; pl[warp] = l_run; }
    __syncthreads();

    // merge 8 warp partials (empty warps: pm=-1e30, pl=0, acc=0)
    float M = pm[0];
    #pragma unroll
    for (int w = 1; w < 8; w++) M = fmaxf(M, pm[w]);
    float scale[8]; float L = 0.f;
    #pragma unroll
    for (int w = 0; w < 8; w++) {
        scale[w] = __expf(pm[w] - M);
        L = fmaf(pl[w], scale[w], L);
    }
    size_t ob = (size_t)idxc * D;
    for (int d = tid; d < D; d += 256) {
        float vsum = 0.f;
        #pragma unroll
        for (int w = 0; w < 8; w++)
            vsum = fmaf(pacc[w][d], scale[w], vsum);
        g_acc[ob + d] = vsum;
    }
    if (tid == 0) { g_m[idxc] = M; g_l[idxc] = L; }
}

// ---------------- kernel 2: combine partial softmax, write att into x -------
__global__ void attn_combine() {
    int a = blockIdx.x, tid = threadIdx.x;
    __shared__ float sscale[NCH];
    __shared__ float sLinv;
    if (tid == 0) {
        float M = -1e30f;
        #pragma unroll
        for (int c = 0; c < NCH; c++) M = fmaxf(M, g_m[a * NCH + c]);
        float L = 0.f;
        #pragma unroll
        for (int c = 0; c < NCH; c++) {
            float lc = g_l[a * NCH + c];
            float s = (lc > 0.f) ? expf(g_m[a * NCH + c] - M) : 0.f;
            sscale[c] = s;
            L += lc * s;
        }
        sLinv = 1.f / L;
    }
    __syncthreads();
    float inv = sLinv;
    for (int d = tid; d < D; d += 256) {
        float v = 0.f;
        #pragma unroll
        for (int c = 0; c < NCH; c++)
            v = fmaf(g_acc[(size_t)(a * NCH + c) * D + d], sscale[c], v);
        g_x[a * 2 * D + d] = v * inv;
    }
}

// ---------------- kernel 3: dense GEMM split-K partials (KT=24, grid 288) ---
__global__ void dense_partial(const float* __restrict__ Wd) {
    int jt = blockIdx.x;   // 0..11 -> j tile of 64
    int kt = blockIdx.y;   // 0..23 -> k slice of 64
    int tid = threadIdx.x;
    int j0 = jt * NTILE, k0 = kt * 64;
    __shared__ float xs[128][32];
    __shared__ float wst[32][NTILE + 1];
    int tj = tid & 31, tg = tid >> 5;
    float c0[16], c1[16];
    #pragma unroll
    for (int i = 0; i < 16; i++) { c0[i] = 0.f; c1[i] = 0.f; }

    for (int kk = 0; kk < 2; kk++) {
        __syncthreads();
        int kb = k0 + kk * 32;
        #pragma unroll
        for (int i = 0; i < 16; i++) {
            int idx = tid + i * 256;
            int aa = idx >> 5, k = idx & 31;
            xs[aa][k] = g_x[(size_t)aa * (2 * D) + kb + k];
        }
        #pragma unroll
        for (int i = 0; i < 8; i++) {
            int idx = tid + i * 256;
            int j = idx >> 5, k = idx & 31;
            wst[k][j] = Wd[(size_t)(j0 + j) * (2 * D) + kb + k];
        }
        __syncthreads();
        #pragma unroll
        for (int k = 0; k < 32; k++) {
            float w0 = wst[k][tj], w1 = wst[k][tj + 32];
            #pragma unroll
            for (int i = 0; i < 16; i++) {
                float xv = xs[tg + 8 * i][k];
                c0[i] = fmaf(xv, w0, c0[i]);
                c1[i] = fmaf(xv, w1, c1[i]);
            }
        }
    }
    size_t base = (size_t)kt * A * D;
    #pragma unroll
    for (int i = 0; i < 16; i++) {
        int aa = tg + 8 * i;
        g_hpart[base + (size_t)aa * D + j0 + tj] = c0[i];
        g_hpart[base + (size_t)aa * D + j0 + 32 + tj] = c1[i];
    }
}

// ---------------- kernel 4: fused split-K reduce + tanh + vocab head --------
__global__ void __launch_bounds__(768) tail_kernel(const float* __restrict__ bd,
                                                   const float* __restrict__ Wp,
                                                   const float* __restrict__ bp,
                                                   const int* __restrict__ lwords,
                                                   const float* __restrict__ Wlab,
                                                   float* __restrict__ out) {
    int a = blockIdx.x, tid = threadIdx.x;
    __shared__ __align__(16) float hs[D];
    __shared__ float4 redsm[768];
    __shared__ float lp[NL * LW];

    int q = tid % 192;          // float4 index within the 768-wide row
    int g = tid / 192;          // slice group 0..3 (6 slices each)

    float4 s = make_float4(0.f, 0.f, 0.f, 0.f);
    #pragma unroll
    for (int t = g * 6; t < g * 6 + 6; t++) {
        float4 v = *(const float4*)(g_hpart + (size_t)t * A * D + (size_t)a * D + q * 4);
        s.x += v.x; s.y += v.y; s.z += v.z; s.w += v.w;
    }
    redsm[tid] = s;
    __syncthreads();
    if (g == 0) {
        float4 b = *(const float4*)(bd + q * 4);
        float4 s1 = redsm[q + 192], s2 = redsm[q + 384], s3 = redsm[q + 576];
        float4 r;
        r.x = tanhf(b.x + s.x + s1.x + s2.x + s3.x);
        r.y = tanhf(b.y + s.y + s1.y + s2.y + s3.y);
        r.z = tanhf(b.z + s.z + s1.z + s2.z + s3.z);
        r.w = tanhf(b.w + s.w + s1.w + s2.w + s3.w);
        *(float4*)(hs + q * 4) = r;
    }
    __syncthreads();

    int warp = tid >> 5, lane = tid & 31;   // 24 warps
    const float4* h4 = (const float4*)hs;
    for (int t = warp; t < NL * LW; t += 24) {
        int word = lwords[t];
        const float4* wr = (const float4*)(Wp + (size_t)word * D);
        float acc = 0.f;
        #pragma unroll
        for (int k = 0; k < 6; k++) {
            float4 v = wr[lane + 32 * k];
            float4 u = h4[lane + 32 * k];
            acc = fmaf(v.x, u.x, acc); acc = fmaf(v.y, u.y, acc);
            acc = fmaf(v.z, u.z, acc); acc = fmaf(v.w, u.w, acc);
        }
        #pragma unroll
        for (int off = 16; off; off >>= 1)
            acc += __shfl_xor_sync(0xffffffffu, acc, off);
        if (lane == 0) lp[t] = tanhf(acc + bp[word]);
    }
    __syncthreads();
    if (tid < 2 * NL) {
        int k = tid / NL, l = tid % NL;
        float o = 0.f;
        #pragma unroll
        for (int w = 0; w < LW; w++)
            o = fmaf(lp[l * LW + w], Wlab[(l * 2 + k) * LW + w], o);
        out[2 * A + a * (2 * NL) + k * NL + l] = o;
    }
}

// ---------------------------------------------------------------------------
extern "C" void kernel_launch(void* const* d_in, const int* in_sizes, int n_in,
                              void* d_out, int out_size) {
    const float* bert   = (const float*)d_in[0];
    const int*   ids    = (const int*)d_in[1];
    const int*   length = (const int*)d_in[2];
    const int*   lwords = (const int*)d_in[3];
    const float* Wsen   = (const float*)d_in[4];
    const float* bsen   = (const float*)d_in[5];
    const float* Wd     = (const float*)d_in[6];
    const float* bd     = (const float*)d_in[7];
    const float* Wp     = (const float*)d_in[8];
    const float* bp     = (const float*)d_in[9];
    const float* Wlab   = (const float*)d_in[10];
    float* out = (float*)d_out;

    attn_fused<<<dim3(NCH, A), 256>>>(bert, ids, length, Wsen, bsen, out);
    attn_combine<<<A, 256>>>();
    dense_partial<<<dim3(JT, KT), 256>>>(Wd);
    tail_kernel<<<A, 768>>>(bd, Wp, bp, lwords, Wlab, out);
}

// round 15
// speedup vs baseline: 1.3029x; 1.0428x over previous
#include <cuda_runtime.h>

#define A 128
#define S 512
#define D 768
#define V 30522
#define NL 10
#define LW 5
#define MASK_ID 103

#define NCH 8          // attention s-chunks per row
#define CHUNK 64
#define JT 12          // dense j tiles (64 each)
#define KT 24          // dense k splits (64 each)
#define NTILE 64

// ---------------- scratch (device globals; no allocs allowed) ---------------
__device__ float g_m[A * NCH];
__device__ float g_l[A * NCH];
__device__ float g_acc[A * NCH * D];
__device__ float g_x[A * 2 * D];          // [att | mask_logit]
__device__ float g_hpart[KT * A * D];

// ---------------- kernel 1: fused prep + online attention, paired rows ------
__global__ void __launch_bounds__(256, 2) attn_fused(const float* __restrict__ bert,
                                                     const int* __restrict__ ids,
                                                     const int* __restrict__ length,
                                                     const float* __restrict__ Wsen,
                                                     const float* __restrict__ bsen,
                                                     float* __restrict__ out) {
    int c = blockIdx.x, a = blockIdx.y, tid = threadIdx.x;
    int warp = tid >> 5, lane = tid & 31;
    int len = length[a];
    int s_lo = max(3, c * CHUNK);
    int s_hi = min((c + 1) * CHUNK, 3 + len);
    int idxc = a * NCH + c;
    if (s_lo >= s_hi) {
        if (tid == 0) { g_m[idxc] = -1e30f; g_l[idxc] = 0.f; }
        return;
    }

    __shared__ int mp;
    __shared__ __align__(16) float mls[D];
    __shared__ __align__(16) float pacc[8][D];
    __shared__ float pm[8], pl[8];
    __shared__ float red0[8], red1[8];

    if (tid == 0) mp = S;
    __syncthreads();
    #pragma unroll
    for (int s = tid; s < S; s += 256)
        if (ids[a * S + s] == MASK_ID) atomicMin(&mp, s);
    __syncthreads();

    const float* mlrow = bert + ((size_t)a * S + mp) * D;
    for (int d = tid; d < D; d += 256) mls[d] = mlrow[d];
    __syncthreads();

    if (c == 0) {
        for (int d = tid; d < D; d += 256)
            g_x[a * 2 * D + D + d] = mls[d];
        const float* r0 = bert + (size_t)a * S * D;
        float p0 = 0.f, p1 = 0.f;
        for (int d = tid; d < D; d += 256) {
            float v = r0[d];
            p0 = fmaf(v, Wsen[d], p0);
            p1 = fmaf(v, Wsen[D + d], p1);
        }
        #pragma unroll
        for (int off = 16; off; off >>= 1) {
            p0 += __shfl_xor_sync(0xffffffffu, p0, off);
            p1 += __shfl_xor_sync(0xffffffffu, p1, off);
        }
        if (lane == 0) { red0[warp] = p0; red1[warp] = p1; }
        __syncthreads();
        if (tid == 0) {
            float s0 = 0.f, s1 = 0.f;
            #pragma unroll
            for (int i = 0; i < 8; i++) { s0 += red0[i]; s1 += red1[i]; }
            out[a * 2 + 0] = s0 + bsen[0];
            out[a * 2 + 1] = s1 + bsen[1];
        }
    }

    const float4* ml4 = (const float4*)mls;

    float m_run = -1e30f, l_run = 0.f;
    float acc[24];
    #pragma unroll
    for (int i = 0; i < 24; i++) acc[i] = 0.f;

    int s = s_lo + warp;
    // paired rows: s and s+8 (12 LDG.128 in flight per warp)
    for (; s + 8 < s_hi; s += 16) {
        const float4* r1 = (const float4*)(bert + ((size_t)a * S + s) * D);
        const float4* r2 = (const float4*)(bert + ((size_t)a * S + s + 8) * D);
        float4 v1[6], v2[6];
        #pragma unroll
        for (int k = 0; k < 6; k++) { v1[k] = r1[lane + 32 * k]; v2[k] = r2[lane + 32 * k]; }
        float s1 = 0.f, s2 = 0.f;
        #pragma unroll
        for (int k = 0; k < 6; k++) {
            float4 u = ml4[lane + 32 * k];
            s1 = fmaf(v1[k].x, u.x, s1); s1 = fmaf(v1[k].y, u.y, s1);
            s1 = fmaf(v1[k].z, u.z, s1); s1 = fmaf(v1[k].w, u.w, s1);
            s2 = fmaf(v2[k].x, u.x, s2); s2 = fmaf(v2[k].y, u.y, s2);
            s2 = fmaf(v2[k].z, u.z, s2); s2 = fmaf(v2[k].w, u.w, s2);
        }
        #pragma unroll
        for (int off = 16; off; off >>= 1) {
            s1 += __shfl_xor_sync(0xffffffffu, s1, off);
            s2 += __shfl_xor_sync(0xffffffffu, s2, off);
        }
        float m_new = fmaxf(m_run, fmaxf(s1, s2));
        float f  = __expf(m_run - m_new);
        float e1 = __expf(s1 - m_new);
        float e2 = __expf(s2 - m_new);
        l_run = fmaf(l_run, f, e1 + e2);
        #pragma unroll
        for (int k = 0; k < 6; k++) {
            acc[4*k+0] = fmaf(e2, v2[k].x, fmaf(e1, v1[k].x, acc[4*k+0] * f));
            acc[4*k+1] = fmaf(e2, v2[k].y, fmaf(e1, v1[k].y, acc[4*k+1] * f));
            acc[4*k+2] = fmaf(e2, v2[k].z, fmaf(e1, v1[k].z, acc[4*k+2] * f));
            acc[4*k+3] = fmaf(e2, v2[k].w, fmaf(e1, v1[k].w, acc[4*k+3] * f));
        }
        m_run = m_new;
    }
    if (s < s_hi) {                         // tail row
        const float4* r1 = (const float4*)(bert + ((size_t)a * S + s) * D);
        float4 v1[6];
        #pragma unroll
        for (int k = 0; k < 6; k++) v1[k] = r1[lane + 32 * k];
        float s1 = 0.f;
        #pragma unroll
        for (int k = 0; k < 6; k++) {
            float4 u = ml4[lane + 32 * k];
            s1 = fmaf(v1[k].x, u.x, s1); s1 = fmaf(v1[k].y, u.y, s1);
            s1 = fmaf(v1[k].z, u.z, s1); s1 = fmaf(v1[k].w, u.w, s1);
        }
        #pragma unroll
        for (int off = 16; off; off >>= 1)
            s1 += __shfl_xor_sync(0xffffffffu, s1, off);
        float m_new = fmaxf(m_run, s1);
        float f  = __expf(m_run - m_new);
        float e1 = __expf(s1 - m_new);
        l_run = fmaf(l_run, f, e1);
        #pragma unroll
        for (int k = 0; k < 6; k++) {
            acc[4*k+0] = fmaf(e1, v1[k].x, acc[4*k+0] * f);
            acc[4*k+1] = fmaf(e1, v1[k].y, acc[4*k+1] * f);
            acc[4*k+2] = fmaf(e1, v1[k].z, acc[4*k+2] * f);
            acc[4*k+3] = fmaf(e1, v1[k].w, acc[4*k+3] * f);
        }
        m_run = m_new;
    }

    float4* pa = (float4*)pacc[warp];
    #pragma unroll
    for (int k = 0; k < 6; k++)
        pa[lane + 32 * k] = make_float4(acc[4*k], acc[4*k+1], acc[4*k+2], acc[4*k+3]);
    if (lane == 0) { pm[warp] = m_run; pl[warp] = l_run; }
    __syncthreads();

    float M = pm[0];
    #pragma unroll
    for (int w = 1; w < 8; w++) M = fmaxf(M, pm[w]);
    float scale[8]; float L = 0.f;
    #pragma unroll
    for (int w = 0; w < 8; w++) {
        scale[w] = __expf(pm[w] - M);
        L = fmaf(pl[w], scale[w], L);
    }
    size_t ob = (size_t)idxc * D;
    for (int d = tid; d < D; d += 256) {
        float vsum = 0.f;
        #pragma unroll
        for (int w = 0; w < 8; w++)
            vsum = fmaf(pacc[w][d], scale[w], vsum);
        g_acc[ob + d] = vsum;
    }
    if (tid == 0) { g_m[idxc] = M; g_l[idxc] = L; }
}

// ---------------- kernel 2: combine partial softmax, write att into x -------
__global__ void attn_combine() {
    int a = blockIdx.x, tid = threadIdx.x;
    __shared__ float sscale[NCH];
    __shared__ float sLinv;
    if (tid == 0) {
        float M = -1e30f;
        #pragma unroll
        for (int c = 0; c < NCH; c++) M = fmaxf(M, g_m[a * NCH + c]);
        float L = 0.f;
        #pragma unroll
        for (int c = 0; c < NCH; c++) {
            float lc = g_l[a * NCH + c];
            float s = (lc > 0.f) ? expf(g_m[a * NCH + c] - M) : 0.f;
            sscale[c] = s;
            L += lc * s;
        }
        sLinv = 1.f / L;
    }
    __syncthreads();
    float inv = sLinv;
    for (int d = tid; d < D; d += 256) {
        float v = 0.f;
        #pragma unroll
        for (int c = 0; c < NCH; c++)
            v = fmaf(g_acc[(size_t)(a * NCH + c) * D + d], sscale[c], v);
        g_x[a * 2 * D + d] = v * inv;
    }
}

// ---------------- kernel 3: dense GEMM split-K partials (KT=24, grid 288) ---
__global__ void dense_partial(const float* __restrict__ Wd) {
    int jt = blockIdx.x;   // 0..11 -> j tile of 64
    int kt = blockIdx.y;   // 0..23 -> k slice of 64
    int tid = threadIdx.x;
    int j0 = jt * NTILE, k0 = kt * 64;
    __shared__ float xs[128][32];
    __shared__ float wst[32][NTILE + 1];
    int tj = tid & 31, tg = tid >> 5;
    float c0[16], c1[16];
    #pragma unroll
    for (int i = 0; i < 16; i++) { c0[i] = 0.f; c1[i] = 0.f; }

    for (int kk = 0; kk < 2; kk++) {
        __syncthreads();
        int kb = k0 + kk * 32;
        #pragma unroll
        for (int i = 0; i < 16; i++) {
            int idx = tid + i * 256;
            int aa = idx >> 5, k = idx & 31;
            xs[aa][k] = g_x[(size_t)aa * (2 * D) + kb + k];
        }
        #pragma unroll
        for (int i = 0; i < 8; i++) {
            int idx = tid + i * 256;
            int j = idx >> 5, k = idx & 31;
            wst[k][j] = Wd[(size_t)(j0 + j) * (2 * D) + kb + k];
        }
        __syncthreads();
        #pragma unroll
        for (int k = 0; k < 32; k++) {
            float w0 = wst[k][tj], w1 = wst[k][tj + 32];
            #pragma unroll
            for (int i = 0; i < 16; i++) {
                float xv = xs[tg + 8 * i][k];
                c0[i] = fmaf(xv, w0, c0[i]);
                c1[i] = fmaf(xv, w1, c1[i]);
            }
        }
    }
    size_t base = (size_t)kt * A * D;
    #pragma unroll
    for (int i = 0; i < 16; i++) {
        int aa = tg + 8 * i;
        g_hpart[base + (size_t)aa * D + j0 + tj] = c0[i];
        g_hpart[base + (size_t)aa * D + j0 + 32 + tj] = c1[i];
    }
}

// ---------------- kernel 4: fused split-K reduce + tanh + vocab head --------
__global__ void __launch_bounds__(768) tail_kernel(const float* __restrict__ bd,
                                                   const float* __restrict__ Wp,
                                                   const float* __restrict__ bp,
                                                   const int* __restrict__ lwords,
                                                   const float* __restrict__ Wlab,
                                                   float* __restrict__ out) {
    int a = blockIdx.x, tid = threadIdx.x;
    __shared__ __align__(16) float hs[D];
    __shared__ float4 redsm[768];
    __shared__ float lp[NL * LW];

    int q = tid % 192;          // float4 index within the 768-wide row
    int g = tid / 192;          // slice group 0..3 (6 slices each)

    float4 s = make_float4(0.f, 0.f, 0.f, 0.f);
    #pragma unroll
    for (int t = g * 6; t < g * 6 + 6; t++) {
        float4 v = *(const float4*)(g_hpart + (size_t)t * A * D + (size_t)a * D + q * 4);
        s.x += v.x; s.y += v.y; s.z += v.z; s.w += v.w;
    }
    redsm[tid] = s;
    __syncthreads();
    if (g == 0) {
        float4 b = *(const float4*)(bd + q * 4);
        float4 s1 = redsm[q + 192], s2 = redsm[q + 384], s3 = redsm[q + 576];
        float4 r;
        r.x = tanhf(b.x + s.x + s1.x + s2.x + s3.x);
        r.y = tanhf(b.y + s.y + s1.y + s2.y + s3.y);
        r.z = tanhf(b.z + s.z + s1.z + s2.z + s3.z);
        r.w = tanhf(b.w + s.w + s1.w + s2.w + s3.w);
        *(float4*)(hs + q * 4) = r;
    }
    __syncthreads();

    int warp = tid >> 5, lane = tid & 31;   // 24 warps
    const float4* h4 = (const float4*)hs;
    for (int t = warp; t < NL * LW; t += 24) {
        int word = lwords[t];
        const float4* wr = (const float4*)(Wp + (size_t)word * D);
        float acc = 0.f;
        #pragma unroll
        for (int k = 0; k < 6; k++) {
            float4 v = wr[lane + 32 * k];
            float4 u = h4[lane + 32 * k];
            acc = fmaf(v.x, u.x, acc); acc = fmaf(v.y, u.y, acc);
            acc = fmaf(v.z, u.z, acc); acc = fmaf(v.w, u.w, acc);
        }
        #pragma unroll
        for (int off = 16; off; off >>= 1)
            acc += __shfl_xor_sync(0xffffffffu, acc, off);
        if (lane == 0) lp[t] = tanhf(acc + bp[word]);
    }
    __syncthreads();
    if (tid < 2 * NL) {
        int k = tid / NL, l = tid % NL;
        float o = 0.f;
        #pragma unroll
        for (int w = 0; w < LW; w++)
            o = fmaf(lp[l * LW + w], Wlab[(l * 2 + k) * LW + w], o);
        out[2 * A + a * (2 * NL) + k * NL + l] = o;
    }
}

// ---------------------------------------------------------------------------
extern "C" void kernel_launch(void* const* d_in, const int* in_sizes, int n_in,
                              void* d_out, int out_size) {
    const float* bert   = (const float*)d_in[0];
    const int*   ids    = (const int*)d_in[1];
    const int*   length = (const int*)d_in[2];
    const int*   lwords = (const int*)d_in[3];
    const float* Wsen   = (const float*)d_in[4];
    const float* bsen   = (const float*)d_in[5];
    const float* Wd     = (const float*)d_in[6];
    const float* bd     = (const float*)d_in[7];
    const float* Wp     = (const float*)d_in[8];
    const float* bp     = (const float*)d_in[9];
    const float* Wlab   = (const float*)d_in[10];
    float* out = (float*)d_out;

    attn_fused<<<dim3(NCH, A), 256>>>(bert, ids, length, Wsen, bsen, out);
    attn_combine<<<A, 256>>>();
    dense_partial<<<dim3(JT, KT), 256>>>(Wd);
    tail_kernel<<<A, 768>>>(bd, Wp, bp, lwords, Wlab, out);
}